// round 14
// baseline (speedup 1.0000x reference)
#include <cuda_runtime.h>
#include <cuda_bf16.h>
#include <cstdint>

// Fixed shapes: B=16, T=512, D=384, MAX_LEN=4096
#define LR_B       16
#define LR_T       512
#define LR_D4      96                        // float4 per row
#define LR_MAXLEN  4096
#define LR_NEXP    (LR_B * LR_MAXLEN * 384)  // 25,165,824 floats

#define NB_SCAN    LR_B                      // 16 scan blocks (bids 0..15)
#define NB_TOK     1024                      // 8 token-warps per block
#define NB_ZERO    8192                      // 8 zero-rows per block
#define MAX_MEL    3584                      // 512 * 7: rows >= this are always 0

__device__ int g_cum[LR_B * LR_T];
__device__ int g_mel[LR_B];
__device__ int g_flag[LR_B];                 // 0 -> 1 (release) when batch ready

__device__ __forceinline__ void flag_release(int* f) {
    asm volatile("st.release.gpu.global.b32 [%0], %1;" :: "l"(f), "r"(1) : "memory");
}
__device__ __forceinline__ void flag_acquire_wait(const int* f) {
    int r;
    asm volatile("ld.acquire.gpu.global.b32 %0, [%1];" : "=r"(r) : "l"(f) : "memory");
    while (r == 0) {
        __nanosleep(100);
        asm volatile("ld.acquire.gpu.global.b32 %0, [%1];" : "=r"(r) : "l"(f) : "memory");
    }
}

// ---------------------------------------------------------------------------
// Single kernel.
//  bids [0,16):        per-batch scan (256 thr, int2 pairs), publish + release
//  bids [16,16+1024):  token path — 1 token/warp, acquire batch flag
//  bids [.., +8192):   zero path — 1 row/warp; pos>=3584 needs no flag at all
// ---------------------------------------------------------------------------
__global__ __launch_bounds__(256)
void lr_all_kernel(const float4* __restrict__ enc,
                   const int*    __restrict__ dur,
                   float4*       __restrict__ out,
                   float*        __restrict__ out_tail) {
    const int bid  = blockIdx.x;
    const int warp = threadIdx.x >> 5;
    const int lane = threadIdx.x & 31;

    if (bid < NB_SCAN) {
        // ---- scan path: batch = bid, 256 threads x 2 durations ----
        __shared__ int wsum[8];
        const int b = bid, t = threadIdx.x;

        const int2 d = ((const int2*)dur)[b * 256 + t];
        int v = d.x + d.y;
        #pragma unroll
        for (int off = 1; off < 32; off <<= 1) {
            int n = __shfl_up_sync(0xffffffffu, v, off);
            if (lane >= off) v += n;
        }
        if (lane == 31) wsum[warp] = v;
        __syncthreads();
        if (warp == 0 && lane < 8) {
            int s = wsum[lane];
            #pragma unroll
            for (int off = 1; off < 8; off <<= 1) {
                int n = __shfl_up_sync(0xffu, s, off, 8);
                if (lane >= off) s += n;
            }
            wsum[lane] = s;
        }
        __syncthreads();

        const int incl = v + (warp ? wsum[warp - 1] : 0);   // inclusive over pairs
        ((int2*)g_cum)[b * 256 + t] = make_int2(incl - d.y, incl);
        if (t == 255) {
            g_mel[b] = incl;                                 // grand total
            if (out_tail) out_tail[b] = (float)incl;
        }
        __threadfence();
        __syncthreads();
        if (t == 0) flag_release(&g_flag[b]);
        return;
    }

    if (bid < NB_SCAN + NB_TOK) {
        // ---- token path: 1 token per warp (proven 16.8us body) ----
        const int tok = (bid - NB_SCAN) * 8 + warp;         // 0..8191
        const int b   = tok >> 9;
        const int t   = tok & 511;

        // scan-independent: enc row loads first
        const float4* src = enc + (size_t)tok * LR_D4;
        const float4 v0 = src[lane];
        const float4 v1 = src[lane + 32];
        const float4 v2 = src[lane + 64];

        flag_acquire_wait(&g_flag[b]);

        const int end   = g_cum[tok];
        const int start = t ? g_cum[tok - 1] : 0;
        if (start >= end) return;                           // dur == 0

        float4* dst = out + ((size_t)(b << 12) + start) * LR_D4;
        for (int p = start; p < end; ++p, dst += LR_D4) {
            dst[lane]      = v0;
            dst[lane + 32] = v1;
            dst[lane + 64] = v2;
        }
    } else {
        // ---- zero path: 1 row per warp ----
        const int row = (bid - NB_SCAN - NB_TOK) * 8 + warp; // 0..65535
        const int b   = row >> 12;
        const int pos = row & 4095;

        if (pos < MAX_MEL) {                                 // may be valid
            flag_acquire_wait(&g_flag[b]);
            if (pos < g_mel[b]) return;                      // token warps own it
        }
        // pos >= 3584: unconditionally zero, no wait needed

        const float4 z = make_float4(0.f, 0.f, 0.f, 0.f);
        float4* dst = out + (size_t)row * LR_D4;
        dst[lane]      = z;
        dst[lane + 32] = z;
        dst[lane + 64] = z;
    }
}

extern "C" void kernel_launch(void* const* d_in, const int* in_sizes, int n_in,
                              void* d_out, int out_size) {
    const float4* enc = (const float4*)d_in[0];
    const int* durations = (const int*)d_in[1];
    float* out = (float*)d_out;

    float* out_tail = (out_size >= LR_NEXP + LR_B) ? (out + LR_NEXP) : nullptr;

    lr_all_kernel<<<NB_SCAN + NB_TOK + NB_ZERO, 256>>>(enc, durations,
                                                       (float4*)out, out_tail);
}

// round 15
// speedup vs baseline: 1.5008x; 1.5008x over previous
#include <cuda_runtime.h>
#include <cuda_bf16.h>
#include <cstdint>

// Fixed shapes: B=16, T=512, D=384, MAX_LEN=4096
#define LR_B       16
#define LR_T       512
#define LR_D4      96                        // float4 per row
#define LR_MAXLEN  4096
#define LR_NEXP    (LR_B * LR_MAXLEN * 384)  // 25,165,824 floats

#define NB_TOK     1024                      // 8 tokens per block (1 per warp)
#define ROWS_PER_ZBLK 16
#define NB_ZERO    (LR_B * LR_MAXLEN / ROWS_PER_ZBLK)   // 4096
#define MAX_MEL    3584                      // 512*7: pos >= this is always zero

// ---------------------------------------------------------------------------
// Single fused kernel, segmented grid (R3 structure, cheaper index math).
//  blocks [0, NB_TOK):   8 token-warps. Block computes base = sum(dur[0..t0-1])
//                        ONCE cooperatively; warps add a tiny 8-dur shfl scan.
//                        Enc loads issue before the reduction (latency overlap).
//  blocks [NB_TOK, ..):  16 rows. pos>=3584 -> skip dur read entirely. Else
//                        warp0 reduces 512 durs (int4), broadcast mel, zero
//                        rows with pos >= mel. First block of batch emits mel.
// ---------------------------------------------------------------------------
__global__ __launch_bounds__(256)
void lr_fused2_kernel(const float4* __restrict__ enc,
                      const int*    __restrict__ dur,
                      float4*       __restrict__ out,
                      float*        __restrict__ out_tail) {
    const int warp = threadIdx.x >> 5;
    const int lane = threadIdx.x & 31;

    if (blockIdx.x < NB_TOK) {
        // ---- token path: tokens [tok0, tok0+8), one batch ----
        __shared__ int wsum[8];
        __shared__ int s_base;
        const int tok0 = blockIdx.x * 8;
        const int tok  = tok0 + warp;
        const int b    = tok0 >> 9;
        const int t0   = tok0 & 511;
        const int* __restrict__ db = dur + b * LR_T;

        // issue enc row loads first (independent of everything below)
        const float4* src = enc + (size_t)tok * LR_D4;
        const float4 v0 = src[lane];
        const float4 v1 = src[lane + 32];
        const float4 v2 = src[lane + 64];

        // this warp's 8 local durations + exclusive prefix (lanes 0..7 hold d)
        int d_l = (lane < 8) ? db[t0 + lane] : 0;
        int sc = d_l;
        #pragma unroll
        for (int off = 1; off < 8; off <<= 1) {
            int n = __shfl_up_sync(0xffffffffu, sc, off);
            if (lane >= off) sc += n;
        }
        const int myd   = __shfl_sync(0xffffffffu, d_l, warp);
        const int myexc = warp ? __shfl_sync(0xffffffffu, sc, warp - 1) : 0;

        // block-cooperative base = sum(dur[b][0..t0-1]); t0 multiple of 8
        const int n4 = t0 >> 2;                        // int4 count, <= 126
        int s = 0;
        if (threadIdx.x < n4) {
            const int4 q = ((const int4*)db)[threadIdx.x];
            s = q.x + q.y + q.z + q.w;
        }
        #pragma unroll
        for (int o = 16; o; o >>= 1) s += __shfl_down_sync(0xffffffffu, s, o);
        if (lane == 0) wsum[warp] = s;
        __syncthreads();
        if (threadIdx.x == 0) {
            int tot = 0;
            #pragma unroll
            for (int i = 0; i < 8; ++i) tot += wsum[i];
            s_base = tot;
        }
        __syncthreads();

        if (myd == 0) return;                          // warp-uniform
        const int start = s_base + myexc;
        const int end   = start + myd;

        float4* dst = out + ((size_t)(b << 12) + start) * LR_D4;
        for (int p = start; p < end; ++p, dst += LR_D4) {
            dst[lane]      = v0;
            dst[lane + 32] = v1;
            dst[lane + 64] = v2;
        }
    } else {
        // ---- zero path: 16 consecutive rows, one batch ----
        __shared__ int s_mel;
        const int zid  = blockIdx.x - NB_TOK;          // 0..4095
        const int r0   = zid * ROWS_PER_ZBLK;
        const int b    = r0 >> 12;
        const int pos0 = r0 & 4095;

        int mel = 0;
        if (pos0 < MAX_MEL) {
            if (warp == 0) {
                const int4* __restrict__ db4 = (const int4*)(dur + b * LR_T);
                int s = 0;
                #pragma unroll
                for (int i = 0; i < 4; ++i) {
                    const int4 q = db4[lane + 32 * i];
                    s += q.x + q.y + q.z + q.w;
                }
                #pragma unroll
                for (int o = 16; o; o >>= 1) s += __shfl_down_sync(0xffffffffu, s, o);
                if (lane == 0) {
                    s_mel = s;
                    if (out_tail && pos0 == 0) out_tail[b] = (float)s;
                }
            }
            __syncthreads();
            mel = s_mel;
            if (pos0 + ROWS_PER_ZBLK <= mel) return;   // fully valid span
        }
        // rows with pos >= mel get zeros (pos0 >= MAX_MEL -> mel=0 -> all rows)
        const float4 z = make_float4(0.f, 0.f, 0.f, 0.f);
        const int pr = pos0 + warp * 2;
        float4* dst = out + (size_t)(r0 + warp * 2) * LR_D4;
        #pragma unroll
        for (int i = 0; i < 2; ++i, dst += LR_D4) {
            if (pr + i >= mel) {
                dst[lane]      = z;
                dst[lane + 32] = z;
                dst[lane + 64] = z;
            }
        }
    }
}

extern "C" void kernel_launch(void* const* d_in, const int* in_sizes, int n_in,
                              void* d_out, int out_size) {
    const float4* enc = (const float4*)d_in[0];
    const int* durations = (const int*)d_in[1];
    float* out = (float*)d_out;

    float* out_tail = (out_size >= LR_NEXP + LR_B) ? (out + LR_NEXP) : nullptr;

    lr_fused2_kernel<<<NB_TOK + NB_ZERO, 256>>>(enc, durations,
                                                (float4*)out, out_tail);
}

// round 16
// speedup vs baseline: 1.6605x; 1.1064x over previous
#include <cuda_runtime.h>
#include <cuda_bf16.h>
#include <cstdint>

// Fixed shapes: B=16, T=512, D=384, MAX_LEN=4096
#define LR_B       16
#define LR_T       512
#define LR_D4      96                        // float4 per row
#define LR_MAXLEN  4096
#define LR_NEXP    (LR_B * LR_MAXLEN * 384)  // 25,165,824 floats

#define NB_TOK     1024                      // 8 tokens per block (1 per warp)
#define ROWS_PER_ZBLK 16
#define NB_ZERO    (LR_B * LR_MAXLEN / ROWS_PER_ZBLK)   // 4096
#define MAX_MEL    3584                      // 512*7: pos >= this is always zero

// streaming store (evict-first): output lines are write-once, never re-read
__device__ __forceinline__ void stcs4(float4* p, float4 v) {
    __stcs(p, v);
}

// ---------------------------------------------------------------------------
// Single fused kernel (R15 winning structure + streaming stores).
//  blocks [0, NB_TOK):   8 token-warps. Block computes base = sum(dur[0..t0-1])
//                        ONCE cooperatively; warps add an 8-dur shfl scan.
//                        Enc loads issue before the reduction (latency overlap).
//  blocks [NB_TOK, ..):  16 rows. pos>=3584 -> skip dur read entirely. Else
//                        warp0 reduces 512 durs (int4), broadcast mel, zero
//                        rows with pos >= mel. First block of batch emits mel.
// ---------------------------------------------------------------------------
__global__ __launch_bounds__(256)
void lr_fused3_kernel(const float4* __restrict__ enc,
                      const int*    __restrict__ dur,
                      float4*       __restrict__ out,
                      float*        __restrict__ out_tail) {
    const int warp = threadIdx.x >> 5;
    const int lane = threadIdx.x & 31;

    if (blockIdx.x < NB_TOK) {
        // ---- token path: tokens [tok0, tok0+8), one batch ----
        __shared__ int wsum[8];
        __shared__ int s_base;
        const int tok0 = blockIdx.x * 8;
        const int tok  = tok0 + warp;
        const int b    = tok0 >> 9;
        const int t0   = tok0 & 511;
        const int* __restrict__ db = dur + b * LR_T;

        // issue enc row loads first (independent of everything below)
        const float4* src = enc + (size_t)tok * LR_D4;
        const float4 v0 = __ldg(src + lane);
        const float4 v1 = __ldg(src + lane + 32);
        const float4 v2 = __ldg(src + lane + 64);

        // this warp's 8 local durations + exclusive prefix (lanes 0..7 hold d)
        int d_l = (lane < 8) ? __ldg(db + t0 + lane) : 0;
        int sc = d_l;
        #pragma unroll
        for (int off = 1; off < 8; off <<= 1) {
            int n = __shfl_up_sync(0xffffffffu, sc, off);
            if (lane >= off) sc += n;
        }
        const int myd   = __shfl_sync(0xffffffffu, d_l, warp);
        const int myexc = warp ? __shfl_sync(0xffffffffu, sc, warp - 1) : 0;

        // block-cooperative base = sum(dur[b][0..t0-1]); t0 multiple of 8
        const int n4 = t0 >> 2;                        // int4 count, <= 126
        int s = 0;
        if (threadIdx.x < n4) {
            const int4 q = __ldg((const int4*)db + threadIdx.x);
            s = q.x + q.y + q.z + q.w;
        }
        #pragma unroll
        for (int o = 16; o; o >>= 1) s += __shfl_down_sync(0xffffffffu, s, o);
        if (lane == 0) wsum[warp] = s;
        __syncthreads();
        if (threadIdx.x == 0) {
            int tot = 0;
            #pragma unroll
            for (int i = 0; i < 8; ++i) tot += wsum[i];
            s_base = tot;
        }
        __syncthreads();

        if (myd == 0) return;                          // warp-uniform
        const int start = s_base + myexc;
        const int end   = start + myd;

        float4* dst = out + ((size_t)(b << 12) + start) * LR_D4;
        for (int p = start; p < end; ++p, dst += LR_D4) {
            stcs4(dst + lane,      v0);
            stcs4(dst + lane + 32, v1);
            stcs4(dst + lane + 64, v2);
        }
    } else {
        // ---- zero path: 16 consecutive rows, one batch ----
        __shared__ int s_mel;
        const int zid  = blockIdx.x - NB_TOK;          // 0..4095
        const int r0   = zid * ROWS_PER_ZBLK;
        const int b    = r0 >> 12;
        const int pos0 = r0 & 4095;

        int mel = 0;
        if (pos0 < MAX_MEL) {
            if (warp == 0) {
                const int4* __restrict__ db4 = (const int4*)(dur + b * LR_T);
                int s = 0;
                #pragma unroll
                for (int i = 0; i < 4; ++i) {
                    const int4 q = __ldg(db4 + lane + 32 * i);
                    s += q.x + q.y + q.z + q.w;
                }
                #pragma unroll
                for (int o = 16; o; o >>= 1) s += __shfl_down_sync(0xffffffffu, s, o);
                if (lane == 0) {
                    s_mel = s;
                    if (out_tail && pos0 == 0) out_tail[b] = (float)s;
                }
            }
            __syncthreads();
            mel = s_mel;
            if (pos0 + ROWS_PER_ZBLK <= mel) return;   // fully valid span
        }
        // rows with pos >= mel get zeros (pos0 >= MAX_MEL -> mel=0 -> all rows)
        const float4 z = make_float4(0.f, 0.f, 0.f, 0.f);
        const int pr = pos0 + warp * 2;
        float4* dst = out + (size_t)(r0 + warp * 2) * LR_D4;
        #pragma unroll
        for (int i = 0; i < 2; ++i, dst += LR_D4) {
            if (pr + i >= mel) {
                stcs4(dst + lane,      z);
                stcs4(dst + lane + 32, z);
                stcs4(dst + lane + 64, z);
            }
        }
    }
}

extern "C" void kernel_launch(void* const* d_in, const int* in_sizes, int n_in,
                              void* d_out, int out_size) {
    const float4* enc = (const float4*)d_in[0];
    const int* durations = (const int*)d_in[1];
    float* out = (float*)d_out;

    float* out_tail = (out_size >= LR_NEXP + LR_B) ? (out + LR_NEXP) : nullptr;

    lr_fused3_kernel<<<NB_TOK + NB_ZERO, 256>>>(enc, durations,
                                                (float4*)out, out_tail);
}